// round 2
// baseline (speedup 1.0000x reference)
#include <cuda_runtime.h>
#include <cstdint>
#include <cstddef>

// Problem: x [A=512, T=128, I=768]; 2-layer BiLSTM over A within T chunks,
// hidden state carried across chunks -> 4 chains x 65536 sequential steps.
#define S_TOTAL 65536
#define NCH 32           // CTAs per chain (each owns 8 h-elements = 32 gate rows)

// ---- static device scratch (no runtime allocations allowed) ----
__device__ float XGF[67108864];   // 65536 x 1024  (fwd input contribution; reused L0/L1)
__device__ float XGB[67108864];   // 65536 x 1024  (bwd)
__device__ float YBUF[33554432];  // 65536 x 512   layer-0 outputs [h_f | h_b]
__device__ float ZBUF[262144];    // 512 x 512     last-chunk layer-1 outputs
__device__ float HBUF[2][2][256]; // [chain][slot][h]  double-buffered h broadcast
__device__ unsigned SEQ[2][NCH][32]; // per-CTA step counters, 128B padded

// ---- memory-order helpers ----
__device__ __forceinline__ unsigned ld_acq(const unsigned* p) {
    unsigned v;
    asm volatile("ld.global.acquire.gpu.u32 %0, [%1];" : "=r"(v) : "l"(p) : "memory");
    return v;
}
__device__ __forceinline__ void st_rel(unsigned* p, unsigned v) {
    asm volatile("st.global.release.gpu.u32 [%0], %1;" :: "l"(p), "r"(v) : "memory");
}
__device__ __forceinline__ float sigm(float x)  { return 1.f / (1.f + __expf(-x)); }
__device__ __forceinline__ float tanhx(float x) { return 1.f - 2.f / (1.f + __expf(2.f * x)); }

__global__ void zero_seq() {
    for (int i = threadIdx.x; i < 2 * NCH * 32; i += blockDim.x)
        ((unsigned*)SEQ)[i] = 0;
}

// ============================================================================
// GEMM: C[65536][1024] = A @ W^T + bias, both directions via blockIdx.z.
// mode 0: logical row r -> x at ((r&511)*128 + (r>>9))*768   (x is [A][T][I])
// mode 1: logical row r -> YBUF + r*512
// ============================================================================
#define BM 128
#define BN 64
#define BK 16

__global__ void __launch_bounds__(256) gemm_xg(
    const float* __restrict__ A, int mode, int K,
    const float* __restrict__ Wf, const float* __restrict__ Wb,
    const float* __restrict__ bf, const float* __restrict__ bb)
{
    const float* W    = blockIdx.z ? Wb : Wf;
    const float* bias = blockIdx.z ? bb : bf;
    float*       C    = blockIdx.z ? XGB : XGF;
    const float* Ab   = mode ? (const float*)YBUF : A;

    __shared__ __align__(16) float As[BK][BM + 4];
    __shared__ __align__(16) float Bs[BK][BN + 4];

    int tid = threadIdx.x;
    int m0 = blockIdx.y * BM;
    int n0 = blockIdx.x * BN;

    int r0 = m0 + (tid >> 2);
    int r1 = r0 + 64;
    const float* arow0 = Ab + (mode ? (size_t)r0 * 512
                                    : ((size_t)(r0 & 511) * 128 + (size_t)(r0 >> 9)) * 768);
    const float* arow1 = Ab + (mode ? (size_t)r1 * 512
                                    : ((size_t)(r1 & 511) * 128 + (size_t)(r1 >> 9)) * 768);
    const float* brow  = W + (size_t)(n0 + (tid >> 2)) * K;
    int akq = (tid & 3) * 4;
    int ty = tid >> 4;   // 0..15 -> m subtile
    int tx = tid & 15;   // 0..15 -> n subtile

    float acc[8][4];
#pragma unroll
    for (int i = 0; i < 8; i++)
#pragma unroll
        for (int j = 0; j < 4; j++) acc[i][j] = 0.f;

    for (int k0 = 0; k0 < K; k0 += BK) {
        float4 a0 = *(const float4*)(arow0 + k0 + akq);
        float4 a1 = *(const float4*)(arow1 + k0 + akq);
        float4 b0 = *(const float4*)(brow + k0 + akq);
        __syncthreads();
        int rr = tid >> 2;
        As[akq + 0][rr] = a0.x; As[akq + 1][rr] = a0.y;
        As[akq + 2][rr] = a0.z; As[akq + 3][rr] = a0.w;
        As[akq + 0][rr + 64] = a1.x; As[akq + 1][rr + 64] = a1.y;
        As[akq + 2][rr + 64] = a1.z; As[akq + 3][rr + 64] = a1.w;
        Bs[akq + 0][rr] = b0.x; Bs[akq + 1][rr] = b0.y;
        Bs[akq + 2][rr] = b0.z; Bs[akq + 3][rr] = b0.w;
        __syncthreads();
#pragma unroll
        for (int k = 0; k < BK; k++) {
            float4 av0 = *(const float4*)&As[k][ty * 8];
            float4 av1 = *(const float4*)&As[k][ty * 8 + 4];
            float4 bv  = *(const float4*)&Bs[k][tx * 4];
            float am[8] = {av0.x, av0.y, av0.z, av0.w, av1.x, av1.y, av1.z, av1.w};
            float bn[4] = {bv.x, bv.y, bv.z, bv.w};
#pragma unroll
            for (int i = 0; i < 8; i++)
#pragma unroll
                for (int j = 0; j < 4; j++)
                    acc[i][j] = fmaf(am[i], bn[j], acc[i][j]);
        }
    }

    float4 bias4 = *(const float4*)(bias + n0 + tx * 4);
#pragma unroll
    for (int i = 0; i < 8; i++) {
        size_t r = (size_t)(m0 + ty * 8 + i);
        float4 o;
        o.x = acc[i][0] + bias4.x; o.y = acc[i][1] + bias4.y;
        o.z = acc[i][2] + bias4.z; o.w = acc[i][3] + bias4.w;
        *(float4*)(C + r * 1024 + n0 + tx * 4) = o;
    }
}

// ============================================================================
// Persistent recurrent kernel. Grid = 64 CTAs (2 chains x 32), 128 thr each.
// CTA owns h-slice [cta*8, cta*8+8); gate rows {g*256 + m0 + e}.
// Thread layout: kc = tid&7 (32 k-values each), rg = tid>>3 (2 gate rows).
// fwd row: n = s ; bwd row: n = (s|511) - (s&511)   (per-chunk reversal).
// ============================================================================
__global__ void __launch_bounds__(128, 1) lstm_kernel(
    const float* __restrict__ whhf, const float* __restrict__ whhb, int layer)
{
    int chain = blockIdx.x >> 5;       // 0 = fwd, 1 = bwd
    int cta   = blockIdx.x & 31;
    const float* xg  = chain ? XGB : XGF;
    const float* whh = chain ? whhb : whhf;
    float* ybuf = (layer == 0) ? YBUF : nullptr;
    float* zbuf = ZBUF;

    int tid = threadIdx.x;
    int kc = tid & 7;
    int rg = tid >> 3;
    int m0 = cta * 8;
    int lr0 = rg * 2, lr1 = rg * 2 + 1;
    int grow0 = (lr0 >> 3) * 256 + m0 + (lr0 & 7);
    int grow1 = (lr1 >> 3) * 256 + m0 + (lr1 & 7);

    // one-time: recurrent weight slice into registers (64 fp32 / thread)
    float4 w0[8], w1[8];
#pragma unroll
    for (int i = 0; i < 8; i++) {
        w0[i] = *(const float4*)(whh + (size_t)grow0 * 256 + kc * 32 + i * 4);
        w1[i] = *(const float4*)(whh + (size_t)grow1 * 256 + kc * 32 + i * 4);
    }

    __shared__ __align__(16) float hs[8 * 36];   // padded h staging
    __shared__ float gs[32];                     // reduced gate pre-activations
    float cstate = 0.f;
    float xg0 = 0.f, xg1 = 0.f;                  // only kc==0 lanes carry xg

    if (kc == 0) {
        int n0i = chain ? 511 : 0;
        xg0 = __ldg(xg + (size_t)n0i * 1024 + grow0);
        xg1 = __ldg(xg + (size_t)n0i * 1024 + grow1);
    }

    for (int s = 0; s < S_TOTAL; s++) {
        if (s > 0) {
            if (tid < NCH) {
                const unsigned* sp = &SEQ[chain][tid][0];
                while (ld_acq(sp) < (unsigned)s) { }
            }
            __syncthreads();
            if (tid < 64) {
                const float4* src = ((const float4*)HBUF[chain][(s & 1) ^ 1]) + tid;
                float4 v = __ldcv(src);
                int kk = tid >> 3, q = tid & 7;
                *(float4*)&hs[kk * 36 + q * 4] = v;
            }
            __syncthreads();
        }

        // prefetch next step's xg (latency hidden behind compute + sync)
        float nx0 = 0.f, nx1 = 0.f;
        if (kc == 0 && s + 1 < S_TOTAL) {
            int sn = s + 1;
            int n = chain ? ((sn | 511) - (sn & 511)) : sn;
            nx0 = __ldg(xg + (size_t)n * 1024 + grow0);
            nx1 = __ldg(xg + (size_t)n * 1024 + grow1);
        }

        float a0 = xg0, a1 = xg1;
        if (s > 0) {
#pragma unroll
            for (int i = 0; i < 8; i++) {
                float4 hv = *(const float4*)&hs[kc * 36 + i * 4];
                a0 = fmaf(w0[i].x, hv.x, a0); a0 = fmaf(w0[i].y, hv.y, a0);
                a0 = fmaf(w0[i].z, hv.z, a0); a0 = fmaf(w0[i].w, hv.w, a0);
                a1 = fmaf(w1[i].x, hv.x, a1); a1 = fmaf(w1[i].y, hv.y, a1);
                a1 = fmaf(w1[i].z, hv.z, a1); a1 = fmaf(w1[i].w, hv.w, a1);
            }
        }
#pragma unroll
        for (int d = 1; d < 8; d <<= 1) {
            a0 += __shfl_xor_sync(0xffffffffu, a0, d);
            a1 += __shfl_xor_sync(0xffffffffu, a1, d);
        }
        if (kc == 0) { gs[lr0] = a0; gs[lr1] = a1; }
        __syncthreads();

        if (tid < 8) {
            float gi = gs[tid], gf = gs[8 + tid], gg = gs[16 + tid], go = gs[24 + tid];
            cstate = sigm(gf) * cstate + sigm(gi) * tanhx(gg);
            float h = sigm(go) * tanhx(cstate);
            __stcg(&HBUF[chain][s & 1][m0 + tid], h);
            if (ybuf) {
                int n = chain ? ((s | 511) - (s & 511)) : s;
                __stcg(ybuf + (size_t)n * 512 + chain * 256 + m0 + tid, h);
            } else if ((s >> 9) == 127) {
                int a = chain ? (511 - (s & 511)) : (s & 511);
                zbuf[(size_t)a * 512 + chain * 256 + m0 + tid] = h;
            }
            __threadfence();
        }
        __syncthreads();
        if (tid == 0) st_rel(&SEQ[chain][cta][0], (unsigned)(s + 1));
        if (kc == 0) { xg0 = nx0; xg1 = nx1; }
    }
}

// ============================================================================
// Head: out[a] = softmax( relu-free (z[a] @ w1^T + b1) @ w2^T + b2 )
// ============================================================================
__global__ void __launch_bounds__(128) head_kernel(
    const float* __restrict__ w1, const float* __restrict__ b1,
    const float* __restrict__ w2, const float* __restrict__ b2,
    float* __restrict__ out)
{
    __shared__ float zs[512];
    __shared__ float hd[128];
    __shared__ float lg[13];
    int a = blockIdx.x, tid = threadIdx.x;

    for (int i = tid; i < 512; i += 128) zs[i] = ZBUF[(size_t)a * 512 + i];
    __syncthreads();

    float acc = b1[tid];
    const float* wr = w1 + (size_t)tid * 512;
    for (int k = 0; k < 512; k += 4) {
        acc = fmaf(wr[k],     zs[k],     acc);
        acc = fmaf(wr[k + 1], zs[k + 1], acc);
        acc = fmaf(wr[k + 2], zs[k + 2], acc);
        acc = fmaf(wr[k + 3], zs[k + 3], acc);
    }
    hd[tid] = acc;
    __syncthreads();

    if (tid < 13) {
        float l = b2[tid];
        const float* w2r = w2 + (size_t)tid * 128;
        for (int k = 0; k < 128; k++) l = fmaf(w2r[k], hd[k], l);
        lg[tid] = l;
    }
    __syncthreads();

    if (tid == 0) {
        float mx = lg[0];
        for (int k = 1; k < 13; k++) mx = fmaxf(mx, lg[k]);
        float s = 0.f, e[13];
        for (int k = 0; k < 13; k++) { e[k] = expf(lg[k] - mx); s += e[k]; }
        float inv = 1.f / s;
        for (int k = 0; k < 13; k++) out[(size_t)a * 13 + k] = e[k] * inv;
    }
}

extern "C" void kernel_launch(void* const* d_in, const int* in_sizes, int n_in,
                              void* d_out, int out_size)
{
    const float* x     = (const float*)d_in[0];
    const float* wih0f = (const float*)d_in[1];
    const float* whh0f = (const float*)d_in[2];
    const float* b0f   = (const float*)d_in[3];
    const float* wih0b = (const float*)d_in[4];
    const float* whh0b = (const float*)d_in[5];
    const float* b0b   = (const float*)d_in[6];
    const float* wih1f = (const float*)d_in[7];
    const float* whh1f = (const float*)d_in[8];
    const float* b1f   = (const float*)d_in[9];
    const float* wih1b = (const float*)d_in[10];
    const float* whh1b = (const float*)d_in[11];
    const float* b1b   = (const float*)d_in[12];
    const float* w1    = (const float*)d_in[13];
    const float* bias1 = (const float*)d_in[14];
    const float* w2    = (const float*)d_in[15];
    const float* bias2 = (const float*)d_in[16];
    float* out = (float*)d_out;

    dim3 gg(1024 / BN, 65536 / BM, 2);

    zero_seq<<<1, 256>>>();
    gemm_xg<<<gg, 256>>>(x, 0, 768, wih0f, wih0b, b0f, b0b);
    lstm_kernel<<<64, 128>>>(whh0f, whh0b, 0);
    gemm_xg<<<gg, 256>>>(nullptr, 1, 512, wih1f, wih1b, b1f, b1b);
    zero_seq<<<1, 256>>>();
    lstm_kernel<<<64, 128>>>(whh1f, whh1b, 1);
    head_kernel<<<512, 128>>>(w1, bias1, w2, bias2, out);
}